// round 12
// baseline (speedup 1.0000x reference)
#include <cuda_runtime.h>
#include <cstdint>

#define NLATC 256
#define NLONC 512
#define MMAXC 256
#define LMAXC 256
#define NBAT  256   // 4*64 flattened batch

// Scratch: real part of F only. g_F[(b*256 + m)*256 + k_lat]. 67 MB.
#define FMASK 0xFFFFFFu
__device__ float g_F[1u << 24];

// ---------------------------------------------------------------------------
// Kernel 1: 512-point FFT (real input) per (b,k_lat) row, radix-2 DIF.
// Stores only Re{F}[b][m][k_lat] = (2pi/512) * Re{rfft(x_row)[m]}.
// ---------------------------------------------------------------------------
__global__ __launch_bounds__(256) void sht_fft_kernel(const float* __restrict__ x,
                                                      long long x_elems)
{
    __shared__ float re[512];
    __shared__ float im[512];

    const int row = blockIdx.x;          // b*256 + k_lat
    const int t   = threadIdx.x;         // 0..255

    if ((long long)row * NLONC + NLONC > x_elems) return;   // block-uniform

    const float* xr = x + (size_t)row * NLONC;
    re[t]       = xr[t];
    re[t + 256] = xr[t + 256];
    im[t]       = 0.0f;
    im[t + 256] = 0.0f;
    __syncthreads();

    #pragma unroll
    for (int span = 256; span >= 1; span >>= 1) {
        const int k = t & (span - 1);
        const int i = (((t & ~(span - 1)) << 1) | k) & 511;
        const int j = (i + span) & 511;

        const float ang = -3.14159265358979323846f * (float)k / (float)span;
        float s, c;
        __sincosf(ang, &s, &c);

        const float ar = re[i], ai = im[i];
        const float br = re[j], bi = im[j];
        re[i] = ar + br;
        im[i] = ai + bi;
        const float vr = ar - br;
        const float vi = ai - bi;
        re[j] = vr * c - vi * s;
        im[j] = vr * s + vi * c;
        __syncthreads();
    }

    // DIF output bit-reversed: X[m] at shared index bitrev9(m).
    const int r = (int)(__brev((unsigned)t) >> 23) & 511;
    const float scale = 6.283185307179586f / 512.0f;

    const int b    = row >> 8;
    const int klat = row & 255;
    g_F[(unsigned)((b * 256 + t) * 256 + klat) & FMASK] = scale * re[r];  // t == m
}

// ---------------------------------------------------------------------------
// Kernel 2: out[b][l][m] = sum_k Re{F}[b][k][m] * W[m][l][k]   (REAL output)
// CTA = (m, l-tile of 32). 256 threads; tx/ty derived from FLAT tid so the
// kernel is correct under any launch shape (round-10 bug class eliminated).
// Per-thread 4b x 4l accumulators.
// weight[m,l,k] == 0 for l < m  ->  tiles with l0+32 <= m are pure zeros.
// ---------------------------------------------------------------------------
__global__ __launch_bounds__(256) void sht_leg_kernel(const float* __restrict__ w,
                                                      float* __restrict__ outf,
                                                      long long w_elems,
                                                      long long out_elems)
{
    const int m   = blockIdx.x;           // 0..255
    const int l0  = blockIdx.y * 32;      // 0..224
    const int tid = (int)(threadIdx.z * blockDim.y * blockDim.x
                        + threadIdx.y * blockDim.x + threadIdx.x); // flat, 0..255

    // ---- pure-zero tile fast path ----
    if (l0 + 32 <= m) {
        for (int i = tid; i < 256 * 32; i += 256) {
            const int b = i >> 5;
            const int l = l0 + (i & 31);
            const long long oi = ((long long)b * 256 + l) * 256 + m;
            if (oi < out_elems) outf[oi] = 0.0f;
        }
        return;
    }

    __shared__ float sW[32][64];          // [l][k-tile] (warp-broadcast reads)
    __shared__ float sF[128][65];         // [b][k-tile], padded

    const int tx = tid & 31;              // 0..31 : b = b0 + tx + 32*i
    const int ty = tid >> 5;              // 0..7  : l = l0 + ty*4 + j

    for (int b0 = 0; b0 < 256; b0 += 128) {
        float acc[4][4];                  // [j(l)][i(b)]
        #pragma unroll
        for (int j = 0; j < 4; j++)
            #pragma unroll
            for (int i = 0; i < 4; i++) acc[j][i] = 0.0f;

        for (int k0 = 0; k0 < 256; k0 += 64) {
            __syncthreads();
            // W tile: 32 l x 64 k (coalesced).
            for (int i = tid; i < 32 * 64; i += 256) {
                const int l = i >> 6, k = i & 63;
                const long long wi = ((long long)m * 256 + (l0 + l)) * 256 + (k0 + k);
                sW[l & 31][k & 63] = (wi < w_elems) ? w[wi] : 0.0f;
            }
            // F tile: 128 b x 64 k (coalesced over k).
            for (int i = tid; i < 128 * 64; i += 256) {
                const int b = i >> 6, k = i & 63;
                const unsigned fi = (unsigned)(((b0 + b) * 256 + m) * 256 + (k0 + k));
                sF[b & 127][k & 63] = g_F[fi & FMASK];
            }
            __syncthreads();

            #pragma unroll 4
            for (int k = 0; k < 64; k++) {
                float fr[4];
                #pragma unroll
                for (int i = 0; i < 4; i++) fr[i] = sF[(tx + 32 * i) & 127][k];
                #pragma unroll
                for (int j = 0; j < 4; j++) {
                    const float wv = sW[(ty * 4 + j) & 31][k];
                    #pragma unroll
                    for (int i = 0; i < 4; i++) acc[j][i] += fr[i] * wv;
                }
            }
        }

        // Store real outputs (guarded in output elements = float32 units).
        #pragma unroll
        for (int j = 0; j < 4; j++) {
            #pragma unroll
            for (int i = 0; i < 4; i++) {
                const int b = b0 + tx + 32 * i;
                const int l = l0 + ty * 4 + j;
                const long long oi = ((long long)b * 256 + l) * 256 + m;
                if (oi < out_elems) outf[oi] = acc[j][i];
            }
        }
        __syncthreads();
    }
}

// ---------------------------------------------------------------------------
extern "C" void kernel_launch(void* const* d_in, const int* in_sizes, int n_in,
                              void* d_out, int out_size)
{
    if (n_in < 2 || d_in == nullptr || d_out == nullptr || in_sizes == nullptr)
        return;
    if (d_in[0] == nullptr || d_in[1] == nullptr) return;

    // x (33.5M elems) is 2x weight (16.7M) under both element-count and byte
    // interpretations: larger of the first two -> x.
    int xi = 0, wi = 1;
    if ((long long)in_sizes[1] > (long long)in_sizes[0]) { xi = 1; wi = 0; }

    const float* x = (const float*)d_in[xi];
    const float* w = (const float*)d_in[wi];
    const long long x_elems = (long long)in_sizes[xi];
    const long long w_elems = (long long)in_sizes[wi];

    float* outf = (float*)d_out;
    // Evidence: output buffer = out_size float32 elements = REAL part of ref.
    const long long out_elems = (long long)out_size;

    sht_fft_kernel<<<NBAT * NLATC, 256>>>(x, x_elems);
    sht_leg_kernel<<<dim3(MMAXC, LMAXC / 32), 256>>>(w, outf, w_elems, out_elems);
}

// round 13
// speedup vs baseline: 1.4110x; 1.4110x over previous
#include <cuda_runtime.h>
#include <cstdint>

#define NLATC 256
#define NLONC 512
#define MMAXC 256
#define LMAXC 256
#define NBAT  256   // 4*64 flattened batch

// Scratch: Re{F}[b][m][k_lat]. 67 MB. FMASK keeps every access in-bounds.
#define FMASK 0xFFFFFFu
__device__ float g_F[1u << 24];

// ---------------------------------------------------------------------------
// Kernel 1: 512-pt FFT, 8 rows (same b, consecutive k_lat) per CTA.
// Twiddles computed once per thread, reused across the 8 rows.
// Output store: per thread 8 contiguous k_lat floats -> full 32B sectors.
// ---------------------------------------------------------------------------
__global__ __launch_bounds__(256) void sht_fft_kernel(const float* __restrict__ x,
                                                      long long x_elems)
{
    __shared__ float sRe[8][512];
    __shared__ float sIm[8][512];

    const int bid = blockIdx.x;               // 0..8191
    const int b   = bid >> 5;                 // 0..255
    const int kt0 = (bid & 31) << 3;          // 0,8,...,248
    const int tid = (int)(threadIdx.z * blockDim.y * blockDim.x
                        + threadIdx.y * blockDim.x + threadIdx.x); // flat

    // Block-uniform guard (before any __syncthreads).
    if ((long long)(bid + 1) * 4096 > x_elems) return;

    // Load 8 contiguous rows = 4096 floats (fully coalesced float4).
    const float4* xv = (const float4*)(x + (size_t)bid * 4096);
    for (int i = tid; i < 1024; i += 256) {
        const float4 v = xv[i];
        const int base = i * 4;
        const int r = base >> 9, n = base & 511;
        sRe[r][n] = v.x; sRe[r][n + 1] = v.y; sRe[r][n + 2] = v.z; sRe[r][n + 3] = v.w;
        sIm[r][n] = 0.0f; sIm[r][n + 1] = 0.0f; sIm[r][n + 2] = 0.0f; sIm[r][n + 3] = 0.0f;
    }
    __syncthreads();

    // Radix-2 DIF, 9 stages. Thread owns butterfly j = tid for all 8 rows.
    #pragma unroll
    for (int span = 256; span >= 1; span >>= 1) {
        const int kk = tid & (span - 1);
        const int i0 = (((tid & ~(span - 1)) << 1) | kk) & 511;
        const int i1 = (i0 + span) & 511;

        float s, c;
        __sincosf(-3.14159265358979323846f * (float)kk / (float)span, &s, &c);

        #pragma unroll
        for (int r = 0; r < 8; r++) {
            const float ar = sRe[r][i0], ai = sIm[r][i0];
            const float br = sRe[r][i1], bi = sIm[r][i1];
            sRe[r][i0] = ar + br;
            sIm[r][i0] = ai + bi;
            const float vr = ar - br, vi = ai - bi;
            sRe[r][i1] = vr * c - vi * s;
            sIm[r][i1] = vr * s + vi * c;
        }
        __syncthreads();
    }

    // Storage index s holds X[brev9(s)]. Even s <-> m<256. Thread tid takes
    // s=2*tid, m=brev9(s), and stores 8 contiguous k_lat floats (32B).
    const int s2 = tid * 2;
    const int m  = (int)(__brev((unsigned)s2) >> 23);   // < 256
    const float scale = 6.283185307179586f / 512.0f;

    float v[8];
    #pragma unroll
    for (int r = 0; r < 8; r++) v[r] = scale * sRe[r][s2];

    float4* dst = (float4*)&g_F[((unsigned)(b * 256 + m) * 256 + kt0) & FMASK];
    dst[0] = make_float4(v[0], v[1], v[2], v[3]);
    dst[1] = make_float4(v[4], v[5], v[6], v[7]);
}

// ---------------------------------------------------------------------------
// Kernel 2: out[b][l][m] = sum_{k<256} F[b][k][m] * W[m][l][k]
// Parity symmetry: w[m,l,255-k] = (-1)^{l+m} w[m,l,k]  ->
//   out = sum_{k<128} w[m,l,k] * ( F[k] + (-1)^{l+m} F[255-k] )
// CTA = (m, l-tile 32). Tiles: b-chunk 128, k-chunk 32 (of half-range 128).
// Thread: 4 consecutive b (float4) x 4 l. Inner loop: 3x LDS.128 : 16 FMA.
// ---------------------------------------------------------------------------
__global__ __launch_bounds__(256) void sht_leg_kernel(const float* __restrict__ w,
                                                      float* __restrict__ outf,
                                                      long long w_elems,
                                                      long long out_elems)
{
    const int m   = blockIdx.x;           // 0..255
    const int l0  = blockIdx.y * 32;      // 0..224
    const int tid = (int)(threadIdx.z * blockDim.y * blockDim.x
                        + threadIdx.y * blockDim.x + threadIdx.x); // flat 0..255

    // ---- pure-zero tile fast path (weight exactly zero for l < m) ----
    if (l0 + 32 <= m) {
        for (int i = tid; i < 256 * 32; i += 256) {
            const int b = i >> 5;
            const int l = l0 + (i & 31);
            const long long oi = ((long long)b * 256 + l) * 256 + m;
            if (oi < out_elems) outf[oi] = 0.0f;
        }
        return;
    }

    __shared__ float sW [32][36];         // [k][l]  36: 16B-aligned rows
    __shared__ float sFe[32][132];        // [k][b]  even part, 132: aligned
    __shared__ float sFo[32][132];        // [k][b]  odd part

    const int tx = tid & 31;              // b4 = tx*4 (4 consecutive b)
    const int ty = tid >> 5;              // l = l0 + ty*4 + j

    // Parity of (l + m) for j=0; alternates with j. Warp-uniform.
    const int p0 = (l0 + ty * 4 + m) & 1;
    // Shared-pointer swap: Fa feeds j even, Fb feeds j odd.
    const float* Fa = p0 ? &sFo[0][0] : &sFe[0][0];
    const float* Fb = p0 ? &sFe[0][0] : &sFo[0][0];

    for (int b0 = 0; b0 < 256; b0 += 128) {
        float4 acc[4];                    // acc[j] = 4 consecutive b
        #pragma unroll
        for (int j = 0; j < 4; j++) acc[j] = make_float4(0.f, 0.f, 0.f, 0.f);

        for (int k0 = 0; k0 < 128; k0 += 32) {
            __syncthreads();
            // W tile: 32 k x 32 l (gmem coalesced over k).
            for (int i = tid; i < 32 * 32; i += 256) {
                const int k = i & 31, l = i >> 5;
                const long long wi = ((long long)m * 256 + (l0 + l)) * 256 + (k0 + k);
                sW[k][l] = (wi < w_elems) ? w[wi] : 0.0f;
            }
            // F tiles: 128 b x 32 k; build even/odd parts.
            for (int i = tid; i < 128 * 32; i += 256) {
                const int b = i >> 5, k = i & 31;
                const unsigned base = (unsigned)(((b0 + b) * 256 + m) * 256);
                const float lo = g_F[(base + (k0 + k)) & FMASK];
                const float hi = g_F[(base + (255 - k0 - k)) & FMASK];
                sFe[k][b] = lo + hi;
                sFo[k][b] = lo - hi;
            }
            __syncthreads();

            #pragma unroll
            for (int k = 0; k < 32; k++) {
                const float4 fa = *(const float4*)(Fa + k * 132 + tx * 4);
                const float4 fb = *(const float4*)(Fb + k * 132 + tx * 4);
                const float4 wv = *(const float4*)(&sW[k][ty * 4]);
                acc[0].x += wv.x * fa.x; acc[0].y += wv.x * fa.y;
                acc[0].z += wv.x * fa.z; acc[0].w += wv.x * fa.w;
                acc[1].x += wv.y * fb.x; acc[1].y += wv.y * fb.y;
                acc[1].z += wv.y * fb.z; acc[1].w += wv.y * fb.w;
                acc[2].x += wv.z * fa.x; acc[2].y += wv.z * fa.y;
                acc[2].z += wv.z * fa.z; acc[2].w += wv.z * fa.w;
                acc[3].x += wv.w * fb.x; acc[3].y += wv.w * fb.y;
                acc[3].z += wv.w * fb.z; acc[3].w += wv.w * fb.w;
            }
        }

        // Store (guarded in float32 output elements).
        #pragma unroll
        for (int j = 0; j < 4; j++) {
            const int l = l0 + ty * 4 + j;
            const float av[4] = {acc[j].x, acc[j].y, acc[j].z, acc[j].w};
            #pragma unroll
            for (int c = 0; c < 4; c++) {
                const int b = b0 + tx * 4 + c;
                const long long oi = ((long long)b * 256 + l) * 256 + m;
                if (oi < out_elems) outf[oi] = av[c];
            }
        }
        __syncthreads();
    }
}

// ---------------------------------------------------------------------------
extern "C" void kernel_launch(void* const* d_in, const int* in_sizes, int n_in,
                              void* d_out, int out_size)
{
    if (n_in < 2 || d_in == nullptr || d_out == nullptr || in_sizes == nullptr)
        return;
    if (d_in[0] == nullptr || d_in[1] == nullptr) return;

    // x (33.5M elems) is 2x weight (16.7M): larger of the first two -> x.
    int xi = 0, wi = 1;
    if ((long long)in_sizes[1] > (long long)in_sizes[0]) { xi = 1; wi = 0; }

    const float* x = (const float*)d_in[xi];
    const float* w = (const float*)d_in[wi];
    const long long x_elems = (long long)in_sizes[xi];
    const long long w_elems = (long long)in_sizes[wi];

    float* outf = (float*)d_out;
    const long long out_elems = (long long)out_size;  // float32 elements

    sht_fft_kernel<<<NBAT * 32, 256>>>(x, x_elems);   // 8 k_lat rows per CTA
    sht_leg_kernel<<<dim3(MMAXC, LMAXC / 32), 256>>>(w, outf, w_elems, out_elems);
}